// round 16
// baseline (speedup 1.0000x reference)
#include <cuda_runtime.h>
#include <cuda_fp16.h>
#include <math.h>
#include <stdint.h>

// Problem constants
#define S_LEN 2048
#define DIM   1536
#define NH    12
#define HD    128
#define CHALF (HD/2)
#define SEG0  22
#define SEG1  21
#define NSPLIT 3

// ---------------- scratch (device globals) ----------------------------------
__device__ uint32_t g_qraw[S_LEN * DIM / 2];   // q pre-norm, fp16 pairs
__device__ uint32_t g_kraw[S_LEN * DIM / 2];   // k pre-norm, fp16 pairs

__device__ uint4 g_x16[S_LEN * DIM / 8];    // x single fp16
__device__ uint4 g_w16[3 * DIM * DIM / 8];  // wq|wk|wv single fp16
__device__ uint4 g_wo16[DIM * DIM / 8];     // wo single fp16
__device__ uint4 g_q16[S_LEN * DIM / 8];    // Q single fp16 (post norm/rope)
__device__ uint4 g_k16[S_LEN * DIM / 8];    // K single fp16
__device__ uint4 g_v16[S_LEN * DIM / 8];    // V single fp16
__device__ uint4 g_ao16[S_LEN * DIM / 8];   // attn out single fp16
__device__ float g_opart[NSPLIT * S_LEN * DIM];  // split-KV O partials (fp32)
__device__ float g_lpart[NSPLIT * S_LEN * NH];   // split-KV l partials

// ---------------- PTX helpers ------------------------------------------------
__device__ __forceinline__ uint32_t smem_u32(const void* p) {
    uint32_t a;
    asm("{ .reg .u64 t; cvta.to.shared.u64 t, %1; cvt.u32.u64 %0, t; }" : "=r"(a) : "l"(p));
    return a;
}
__device__ __forceinline__ void ldsm_x4(uint32_t* r, uint32_t addr) {
    asm volatile("ldmatrix.sync.aligned.m8n8.x4.shared.b16 {%0,%1,%2,%3}, [%4];"
        : "=r"(r[0]), "=r"(r[1]), "=r"(r[2]), "=r"(r[3]) : "r"(addr));
}
__device__ __forceinline__ void ldsm_x4_t(uint32_t* r, uint32_t addr) {
    asm volatile("ldmatrix.sync.aligned.m8n8.x4.trans.shared.b16 {%0,%1,%2,%3}, [%4];"
        : "=r"(r[0]), "=r"(r[1]), "=r"(r[2]), "=r"(r[3]) : "r"(addr));
}
__device__ __forceinline__ void mma_f16(float* c, const uint32_t* a, const uint32_t* b) {
    asm volatile(
        "mma.sync.aligned.m16n8k16.row.col.f32.f16.f16.f32 "
        "{%0,%1,%2,%3}, {%4,%5,%6,%7}, {%8,%9}, {%0,%1,%2,%3};"
        : "+f"(c[0]), "+f"(c[1]), "+f"(c[2]), "+f"(c[3])
        : "r"(a[0]), "r"(a[1]), "r"(a[2]), "r"(a[3]), "r"(b[0]), "r"(b[1]));
}
__device__ __forceinline__ void cp16(uint32_t dst, const void* src) {
    asm volatile("cp.async.cg.shared.global [%0], [%1], 16;" :: "r"(dst), "l"(src));
}
#define CP_COMMIT()  asm volatile("cp.async.commit_group;" ::: "memory")
#define CP_WAIT(n)   asm volatile("cp.async.wait_group %0;" :: "n"(n) : "memory")

__device__ __forceinline__ uint32_t pack2h(float v0, float v1) {
    __half h0 = __float2half_rn(v0);
    __half h1 = __float2half_rn(v1);
    return (uint32_t)__half_as_ushort(h0) | ((uint32_t)__half_as_ushort(h1) << 16);
}
// p = 2^t for a pair: cvt fp32x2 -> f16x2, then paired MUFU exp
__device__ __forceinline__ uint32_t exp2_pair(float t_lo, float t_hi) {
    uint32_t d;
    asm("cvt.rn.f16x2.f32 %0, %1, %2;" : "=r"(d) : "f"(t_hi), "f"(t_lo));
    asm("ex2.approx.f16x2 %0, %0;" : "+r"(d));
    return d;
}

// ---------------- conversions --------------------------------------------------
__global__ __launch_bounds__(256)
void conv_h1(const float4* __restrict__ src, uint4* __restrict__ dst, int n8)
{
    int idx = blockIdx.x * blockDim.x + threadIdx.x;
    if (idx >= n8) return;
    float4 a = src[2 * idx], b = src[2 * idx + 1];
    dst[idx] = make_uint4(pack2h(a.x, a.y), pack2h(a.z, a.w),
                          pack2h(b.x, b.y), pack2h(b.z, b.w));
}

__global__ __launch_bounds__(256)
void conv_h1_w4(const float4* __restrict__ w0, const float4* __restrict__ w1,
                const float4* __restrict__ w2, const float4* __restrict__ w3,
                uint4* __restrict__ dst012, uint4* __restrict__ dst3, int n8)
{
    int idx = blockIdx.x * blockDim.x + threadIdx.x;
    if (idx >= n8) return;
    int y = blockIdx.y;
    const float4* src = (y == 0) ? w0 : (y == 1) ? w1 : (y == 2) ? w2 : w3;
    uint4* dst = (y < 3) ? (dst012 + (size_t)y * n8) : dst3;
    float4 a = src[2 * idx], b = src[2 * idx + 1];
    dst[idx] = make_uint4(pack2h(a.x, a.y), pack2h(a.z, a.w),
                          pack2h(b.x, b.y), pack2h(b.z, b.w));
}

// ---------------- fp16 1-term GEMM, BK=64, 3-stage ring, late prefetch --------
#define PITCH  144
#define TILEB  (128 * PITCH)
#define STAGEB (2 * TILEB)
#define GEMM_SMEM (3 * STAGEB)
#define NSTAGE 24

__global__ __launch_bounds__(256, 2)
void gemm_mma(const uint4* __restrict__ A16, const uint4* __restrict__ W16,
              const float* __restrict__ b0, const float* __restrict__ b1,
              const float* __restrict__ b2,
              void* __restrict__ C0v, void* __restrict__ C1v,
              uint32_t* __restrict__ V16,
              int ntw, int c_half)
{
    extern __shared__ char smc[];
    const uint32_t sb = smem_u32(smc);
    const int tid  = threadIdx.x;
    const int wid  = tid >> 5;
    const int lane = tid & 31;
    const int warp_m = wid & 3;
    const int warp_n = wid >> 2;

    const int m0     = blockIdx.x * 128;
    const int ntile  = blockIdx.y;
    const int w      = ntile / ntw;
    const int ncol0  = (ntile % ntw) * 128;
    const size_t wrow0 = (size_t)ntile * 128;

    const int lr = tid >> 3;
    const int lj = tid & 7;

    float acc[2][8][4];
#pragma unroll
    for (int i = 0; i < 2; i++)
#pragma unroll
        for (int j = 0; j < 8; j++)
#pragma unroll
            for (int k = 0; k < 4; k++) acc[i][j][k] = 0.f;

    auto prefetch = [&](int c, int buf) {
        const uint32_t st = sb + buf * STAGEB;
        const int kc8 = c * 8;
#pragma unroll
        for (int i = 0; i < 4; i++) {
            int r = lr + i * 32;
            uint32_t so = (uint32_t)(r * PITCH + lj * 16);
            size_t ga = (size_t)(m0 + r) * (DIM / 8) + kc8 + lj;
            cp16(st + 0 * TILEB + so, A16 + ga);
            size_t gb = (wrow0 + r) * (DIM / 8) + kc8 + lj;
            cp16(st + 1 * TILEB + so, W16 + gb);
        }
        CP_COMMIT();
    };

    prefetch(0, 0);
    prefetch(1, 1);

    const uint32_t a_lo = (uint32_t)((warp_m * 32 + (lane & 15)) * PITCH + (lane >> 4) * 16);
    const uint32_t b_lo = (uint32_t)((warp_n * 64 + (lane & 7) + ((lane >> 4) << 3)) * PITCH
                                     + ((lane >> 3) & 1) * 16);

    for (int c = 0; c < NSTAGE; c++) {
        if (c < NSTAGE - 1) { CP_WAIT(1); } else { CP_WAIT(0); }
        __syncthreads();

        const uint32_t st = sb + (c % 3) * STAGEB;

        // ks=0 ldsm FIRST (tensor path starts immediately)...
        uint32_t ah[2][4], bh[4][4];
#pragma unroll
        for (int mt = 0; mt < 2; mt++)
            ldsm_x4(ah[mt], st + mt * (16 * PITCH) + a_lo);
#pragma unroll
        for (int np = 0; np < 4; np++)
            ldsm_x4(bh[np], st + 1 * TILEB + np * (16 * PITCH) + b_lo);

        // ...then issue next-stage prefetch inside the ldsm-latency shadow
        if (c + 2 < NSTAGE) prefetch(c + 2, (c + 2) % 3);

#pragma unroll
        for (int mt = 0; mt < 2; mt++)
#pragma unroll
            for (int nt = 0; nt < 8; nt++) {
                const uint32_t* bhp = &bh[nt >> 1][(nt & 1) * 2];
                mma_f16(acc[mt][nt], ah[mt], bhp);
            }

#pragma unroll
        for (int ks = 1; ks < 4; ks++) {
#pragma unroll
            for (int mt = 0; mt < 2; mt++)
                ldsm_x4(ah[mt], st + mt * (16 * PITCH) + ks * 32 + a_lo);
#pragma unroll
            for (int np = 0; np < 4; np++)
                ldsm_x4(bh[np], st + 1 * TILEB + np * (16 * PITCH) + ks * 32 + b_lo);
#pragma unroll
            for (int mt = 0; mt < 2; mt++)
#pragma unroll
                for (int nt = 0; nt < 8; nt++) {
                    const uint32_t* bhp = &bh[nt >> 1][(nt & 1) * 2];
                    mma_f16(acc[mt][nt], ah[mt], bhp);
                }
        }
    }

    const float* bias = (w == 0) ? b0 : (w == 1) ? b1 : b2;
    const int g = lane >> 2, t4 = lane & 3;

    if (w < 2) {
        if (c_half) {
            uint32_t* C = (uint32_t*)((w == 0) ? C0v : C1v);
#pragma unroll
            for (int mt = 0; mt < 2; mt++) {
                int row = m0 + warp_m * 32 + mt * 16 + g;
#pragma unroll
                for (int nt = 0; nt < 8; nt++) {
                    int col = ncol0 + warp_n * 64 + nt * 8 + t4 * 2;
                    float2 bv = *(const float2*)(bias + col);
                    size_t i0 = ((size_t)row * DIM + col) >> 1;
                    size_t i1 = ((size_t)(row + 8) * DIM + col) >> 1;
                    C[i0] = pack2h(acc[mt][nt][0] + bv.x, acc[mt][nt][1] + bv.y);
                    C[i1] = pack2h(acc[mt][nt][2] + bv.x, acc[mt][nt][3] + bv.y);
                }
            }
        } else {
            float* C = (float*)((w == 0) ? C0v : C1v);
#pragma unroll
            for (int mt = 0; mt < 2; mt++) {
                int row = m0 + warp_m * 32 + mt * 16 + g;
#pragma unroll
                for (int nt = 0; nt < 8; nt++) {
                    int col = ncol0 + warp_n * 64 + nt * 8 + t4 * 2;
                    float2 bv = *(const float2*)(bias + col);
                    float2 o0, o1;
                    o0.x = acc[mt][nt][0] + bv.x;  o0.y = acc[mt][nt][1] + bv.y;
                    o1.x = acc[mt][nt][2] + bv.x;  o1.y = acc[mt][nt][3] + bv.y;
                    *(float2*)(C + (size_t)row * DIM + col)       = o0;
                    *(float2*)(C + (size_t)(row + 8) * DIM + col) = o1;
                }
            }
        }
    } else {
#pragma unroll
        for (int mt = 0; mt < 2; mt++) {
            int row = m0 + warp_m * 32 + mt * 16 + g;
#pragma unroll
            for (int nt = 0; nt < 8; nt++) {
                int col = ncol0 + warp_n * 64 + nt * 8 + t4 * 2;
                float2 bv = *(const float2*)(bias + col);
                size_t i0 = ((size_t)row * DIM + col) >> 1;
                size_t i1 = ((size_t)(row + 8) * DIM + col) >> 1;
                V16[i0] = pack2h(acc[mt][nt][0] + bv.x, acc[mt][nt][1] + bv.y);
                V16[i1] = pack2h(acc[mt][nt][2] + bv.x, acc[mt][nt][3] + bv.y);
            }
        }
    }
}

// ---------------- fused RMSNorm + RoPE (fp16 in) -> single fp16 Q/K -----------
__global__ __launch_bounds__(256)
void norm_rope_split(const uint32_t* __restrict__ Qp, const uint32_t* __restrict__ Kp,
                     const float* __restrict__ gq, const float* __restrict__ gk,
                     const float* __restrict__ freqs, const int* __restrict__ grid_sizes,
                     uint32_t* __restrict__ Q16, uint32_t* __restrict__ K16)
{
    const int s   = blockIdx.x;
    const int tid = threadIdx.x;
    const int lane = tid & 31;
    const int wrp  = tid >> 5;
    __shared__ float redq[8], redk[8];
    __shared__ float s_rq, s_rk;

    const uint32_t* qrow = Qp + (size_t)s * (DIM / 2);
    const uint32_t* krow = Kp + (size_t)s * (DIM / 2);

    float sq = 0.f, sk = 0.f;
    for (int i = tid; i < DIM / 2; i += 256) {
        float2 a = __half22float2(*(const __half2*)(qrow + i));
        float2 b = __half22float2(*(const __half2*)(krow + i));
        sq += a.x * a.x + a.y * a.y;
        sk += b.x * b.x + b.y * b.y;
    }
#pragma unroll
    for (int off = 16; off > 0; off >>= 1) {
        sq += __shfl_xor_sync(0xffffffffu, sq, off);
        sk += __shfl_xor_sync(0xffffffffu, sk, off);
    }
    if (lane == 0) { redq[wrp] = sq; redk[wrp] = sk; }
    __syncthreads();
    if (wrp == 0) {
        float a = (lane < 8) ? redq[lane] : 0.f;
        float b = (lane < 8) ? redk[lane] : 0.f;
#pragma unroll
        for (int off = 4; off > 0; off >>= 1) {
            a += __shfl_xor_sync(0xffffffffu, a, off);
            b += __shfl_xor_sync(0xffffffffu, b, off);
        }
        if (lane == 0) {
            s_rq = rsqrtf(a * (1.f / DIM) + 1e-6f);
            s_rk = rsqrtf(b * (1.f / DIM) + 1e-6f);
        }
    }
    __syncthreads();

    const float rq = s_rq, rk = s_rk;

    const int hdim = grid_sizes[1];
    const int wdim = grid_sizes[2];
    const int wi = s % wdim;
    const int hi = (s / wdim) % hdim;
    const int fi = s / (wdim * hdim);

    for (int p = tid; p < NH * CHALF; p += 256) {
        const int head = p >> 6;
        const int c    = p & 63;
        int pos = (c < SEG0) ? fi : ((c < SEG0 + SEG1) ? hi : wi);
        float ang = freqs[(size_t)pos * CHALF + c];
        float sn, cs;
        __sincosf(ang, &sn, &cs);

        const int i32 = head * CHALF + c;
        const int d0  = 2 * i32;
        float2 qp = __half22float2(*(const __half2*)(qrow + i32));
        float2 kp = __half22float2(*(const __half2*)(krow + i32));
        float2 gqv = *(const float2*)(gq + d0);
        float2 gkv = *(const float2*)(gk + d0);

        float q0 = qp.x * rq * gqv.x;
        float q1 = qp.y * rq * gqv.y;
        float qv0 = q0 * cs - q1 * sn;
        float qv1 = q0 * sn + q1 * cs;

        float k0 = kp.x * rk * gkv.x;
        float k1 = kp.y * rk * gkv.y;
        float kv0 = k0 * cs - k1 * sn;
        float kv1 = k0 * sn + k1 * cs;

        size_t gi = (size_t)s * (DIM / 2) + i32;
        Q16[gi] = pack2h(qv0, qv1);
        K16[gi] = pack2h(kv0, kv1);
    }
}

// ---------------- flash attention: split-KV x3, late prefetch -----------------
#define FQT    128
#define FKT    64
#define FPITCH 272
#define K_O    0
#define V_O    (64 * FPITCH)
#define SLOT_SZ (2 * 64 * FPITCH)
#define FL_SMEM (3 * SLOT_SZ)           // Q staged in slot 2
#define SM_SHIFT 4.0f
#define LOG2E    1.44269504f
#define NT_TOT (S_LEN / FKT)            // 32 tiles total
#define NT_BASE 11                      // z=0:11, z=1:11, z=2:10

__global__ __launch_bounds__(256, 2)
void flash_mma(const uint4* __restrict__ Q16, const uint4* __restrict__ K16,
               const uint4* __restrict__ V16,
               float* __restrict__ Opart, float* __restrict__ Lpart,
               const int* __restrict__ seq_lens, float qscale)
{
    extern __shared__ char smc[];
    const uint32_t sb = smem_u32(smc);
    const int tid  = threadIdx.x;
    const int wid  = tid >> 5;
    const int lane = tid & 31;
    const int g    = lane >> 2;
    const int t4   = lane & 3;
    const int head = blockIdx.y;
    const int q0   = blockIdx.x * FQT;
    const int z    = blockIdx.z;
    const int t0   = z * NT_BASE;
    const int ntl  = (t0 + NT_BASE <= NT_TOT) ? NT_BASE : (NT_TOT - t0);
    const int seqlen = seq_lens[0];

    const int DIM8 = DIM / 8;
    const int h8   = head * (HD / 8);
    const float c2 = qscale * LOG2E;
    const float sh2 = SM_SHIFT * LOG2E;

    // stage Q into slot 2
    const uint32_t qst = sb + 2 * SLOT_SZ;
#pragma unroll
    for (int i = 0; i < 8; i++) {
        int t = tid + 256 * i;
        int r = t >> 4, j = t & 15;
        uint32_t so = (uint32_t)(r * FPITCH + j * 16);
        size_t gi = (size_t)(q0 + r) * DIM8 + h8 + j;
        cp16(qst + so, Q16 + gi);
    }
    CP_COMMIT();

    auto load_kv = [&](int kt, int slot) {
        uint32_t st = sb + slot * SLOT_SZ;
        int kr0 = kt * FKT;
#pragma unroll
        for (int i = 0; i < 4; i++) {
            int t = tid + 256 * i;
            int r = t >> 4, j = t & 15;
            uint32_t so = (uint32_t)(r * FPITCH + j * 16);
            size_t gi = (size_t)(kr0 + r) * DIM8 + h8 + j;
            cp16(st + K_O + so, K16 + gi);
            cp16(st + V_O + so, V16 + gi);
        }
        CP_COMMIT();
    };

    const uint32_t a_off  = (uint32_t)((wid * 16 + (lane & 15)) * FPITCH + (lane >> 4) * 16);
    const uint32_t bk_off = (uint32_t)(((lane & 7) + ((lane >> 4) << 3)) * FPITCH
                                       + ((lane >> 3) & 1) * 16);
    const uint32_t bv_row = (uint32_t)((lane & 7) + (((lane >> 3) & 1) << 3));
    const uint32_t bv_col = (uint32_t)((lane >> 4) * 16);

    CP_WAIT(0);
    __syncthreads();
    uint32_t qf[8][4];
#pragma unroll
    for (int kk = 0; kk < 8; kk++) {
        ldsm_x4(qf[kk], qst + a_off + kk * 32);
    }

    load_kv(t0 + 0, 0);
    load_kv(t0 + 1, 1);

    float o[16][4];
#pragma unroll
    for (int i = 0; i < 16; i++)
#pragma unroll
        for (int j = 0; j < 4; j++) o[i][j] = 0.f;
    float lacc[4] = {0.f, 0.f, 0.f, 0.f};
    const uint32_t ones2[2] = {0x3C003C00u, 0x3C003C00u};

    for (int kt = 0; kt < ntl; kt++) {
        if (kt < ntl - 1) { CP_WAIT(1); } else { CP_WAIT(0); }
        __syncthreads();

        const uint32_t st = sb + (kt % 3) * SLOT_SZ;

        // ---- scores first (tensor path starts immediately at barrier) ----
        float acc[8][4];
#pragma unroll
        for (int i = 0; i < 8; i++)
#pragma unroll
            for (int j = 0; j < 4; j++) acc[i][j] = 0.f;

#pragma unroll
        for (int kk = 0; kk < 8; kk++) {
#pragma unroll
            for (int np = 0; np < 4; np++) {
                uint32_t bh[4];
                ldsm_x4(bh, st + K_O + np * (16 * FPITCH) + bk_off + kk * 32);
                mma_f16(acc[2*np],   qf[kk], &bh[0]);
                mma_f16(acc[2*np+1], qf[kk], &bh[2]);
            }
        }

        // ---- issue next-next tile load now (overlaps softmax + PV) ----
        if (kt + 2 < ntl) load_kv(t0 + kt + 2, (kt + 2) % 3);

        // ---- fixed-shift softmax via paired f16 exp ----
        const int kr0 = (t0 + kt) * FKT;
        uint32_t ph0[8], ph1[8];
#pragma unroll
        for (int j = 0; j < 8; j++) {
            float t00 = fmaf(acc[j][0], c2, -sh2);
            float t01 = fmaf(acc[j][1], c2, -sh2);
            float t10 = fmaf(acc[j][2], c2, -sh2);
            float t11 = fmaf(acc[j][3], c2, -sh2);
            int c0 = kr0 + 8 * j + 2 * t4;
            if (c0 >= seqlen)     { t00 = -1e30f; t10 = -1e30f; }
            if (c0 + 1 >= seqlen) { t01 = -1e30f; t11 = -1e30f; }
            ph0[j] = exp2_pair(t00, t01);
            ph1[j] = exp2_pair(t10, t11);
        }

        // ---- PV + l (ones-column MMA) ----
#pragma unroll
        for (int k2 = 0; k2 < 4; k2++) {
            uint32_t aph[4] = { ph0[2*k2], ph1[2*k2], ph0[2*k2+1], ph1[2*k2+1] };
            mma_f16(lacc, aph, ones2);
            uint32_t vrow = st + V_O + (uint32_t)((k2 * 16 + bv_row) * FPITCH) + bv_col;
#pragma unroll
            for (int d = 0; d < 8; d++) {
                uint32_t bv[4];
                ldsm_x4_t(bv, vrow + d * 32);
                mma_f16(o[2*d],   aph, &bv[0]);
                mma_f16(o[2*d+1], aph, &bv[2]);
            }
        }
    }

    // ---- fp32 partial epilogue ----
    const int row0 = q0 + wid * 16 + g;
    float* Op = Opart + (size_t)z * S_LEN * DIM;
    if (t4 == 0) {
        Lpart[(size_t)z * S_LEN * NH + (size_t)row0 * NH + head]       = lacc[0];
        Lpart[(size_t)z * S_LEN * NH + (size_t)(row0 + 8) * NH + head] = lacc[2];
    }
#pragma unroll
    for (int nt = 0; nt < 16; nt++) {
        int col = head * HD + nt * 8 + 2 * t4;
        *(float2*)(Op + (size_t)row0 * DIM + col)       = make_float2(o[nt][0], o[nt][1]);
        *(float2*)(Op + (size_t)(row0 + 8) * DIM + col) = make_float2(o[nt][2], o[nt][3]);
    }
}

// ---------------- split-KV combine: sum(Oz)/sum(lz) -> fp16 -------------------
__global__ __launch_bounds__(256)
void combine_kv(const float* __restrict__ Opart, const float* __restrict__ Lpart,
                uint32_t* __restrict__ AO16)
{
    int e4 = blockIdx.x * 256 + threadIdx.x;
    if (e4 >= S_LEN * DIM / 4) return;
    size_t base = (size_t)e4 * 4;
    int row = (int)(base / DIM);
    int col = (int)(base % DIM);
    int h = col >> 7;
    float l = 0.f;
    float4 s = make_float4(0.f, 0.f, 0.f, 0.f);
#pragma unroll
    for (int z = 0; z < NSPLIT; z++) {
        l += Lpart[(size_t)z * S_LEN * NH + (size_t)row * NH + h];
        float4 a = *(const float4*)(Opart + (size_t)z * S_LEN * DIM + base);
        s.x += a.x; s.y += a.y; s.z += a.z; s.w += a.w;
    }
    float inv = 1.f / l;
    AO16[e4 * 2 + 0] = pack2h(s.x * inv, s.y * inv);
    AO16[e4 * 2 + 1] = pack2h(s.z * inv, s.w * inv);
}

// ---------------- launcher ---------------------------------------------------
extern "C" void kernel_launch(void* const* d_in, const int* in_sizes, int n_in,
                              void* d_out, int out_size)
{
    const float* x     = (const float*)d_in[0];
    const float* freqs = (const float*)d_in[1];
    const float* wq    = (const float*)d_in[2];
    const float* bq    = (const float*)d_in[3];
    const float* wk    = (const float*)d_in[4];
    const float* bk    = (const float*)d_in[5];
    const float* wv    = (const float*)d_in[6];
    const float* bv    = (const float*)d_in[7];
    const float* wo    = (const float*)d_in[8];
    const float* bo    = (const float*)d_in[9];
    const float* gq    = (const float*)d_in[10];
    const float* gk    = (const float*)d_in[11];
    const int*   seq_lens   = (const int*)d_in[12];
    const int*   grid_sizes = (const int*)d_in[13];
    float* out = (float*)d_out;

    uint32_t *qraw, *kraw;
    float *opart, *lpart;
    uint4 *x16, *w16, *wo16, *q16, *k16, *v16, *ao16;
    cudaGetSymbolAddress((void**)&qraw,  g_qraw);
    cudaGetSymbolAddress((void**)&kraw,  g_kraw);
    cudaGetSymbolAddress((void**)&x16,   g_x16);
    cudaGetSymbolAddress((void**)&w16,   g_w16);
    cudaGetSymbolAddress((void**)&wo16,  g_wo16);
    cudaGetSymbolAddress((void**)&q16,   g_q16);
    cudaGetSymbolAddress((void**)&k16,   g_k16);
    cudaGetSymbolAddress((void**)&v16,   g_v16);
    cudaGetSymbolAddress((void**)&ao16,  g_ao16);
    cudaGetSymbolAddress((void**)&opart, g_opart);
    cudaGetSymbolAddress((void**)&lpart, g_lpart);

    const int n8x = S_LEN * DIM / 8;
    const int n8w = DIM * DIM / 8;
    const float qscale = 1.0f / sqrtf((float)HD);

    conv_h1<<<(n8x + 255) / 256, 256>>>((const float4*)x, x16, n8x);
    conv_h1_w4<<<dim3((n8w + 255) / 256, 4), 256>>>(
        (const float4*)wq, (const float4*)wk, (const float4*)wv, (const float4*)wo,
        w16, wo16, n8w);

    cudaFuncSetAttribute(gemm_mma, cudaFuncAttributeMaxDynamicSharedMemorySize, GEMM_SMEM);

    // fused QKV: q,k written as fp16; V fp16
    gemm_mma<<<dim3(S_LEN / 128, 36), 256, GEMM_SMEM>>>(
        x16, w16, bq, bk, bv, qraw, kraw, (uint32_t*)v16, DIM / 128, 1);

    norm_rope_split<<<S_LEN, 256>>>(qraw, kraw, gq, gk, freqs, grid_sizes,
                                    (uint32_t*)q16, (uint32_t*)k16);

    cudaFuncSetAttribute(flash_mma, cudaFuncAttributeMaxDynamicSharedMemorySize, FL_SMEM);
    flash_mma<<<dim3(S_LEN / FQT, NH, NSPLIT), 256, FL_SMEM>>>(
        q16, k16, v16, opart, lpart, seq_lens, qscale);

    combine_kv<<<(S_LEN * DIM / 4 + 255) / 256, 256>>>(opart, lpart, (uint32_t*)ao16);

    // output projection: fp32 C
    gemm_mma<<<dim3(S_LEN / 128, 12), 256, GEMM_SMEM>>>(
        ao16, wo16, bo, bo, bo, out, (void*)out, (uint32_t*)v16, DIM / 128, 0);
}

// round 17
// speedup vs baseline: 1.0561x; 1.0561x over previous
#include <cuda_runtime.h>
#include <cuda_fp16.h>
#include <math.h>
#include <stdint.h>

// Problem constants
#define S_LEN 2048
#define DIM   1536
#define NH    12
#define HD    128
#define CHALF (HD/2)
#define SEG0  22
#define SEG1  21
#define NSPLIT 3

// ---------------- scratch (device globals) ----------------------------------
__device__ uint32_t g_qraw[S_LEN * DIM / 2];   // q pre-norm, fp16 pairs
__device__ uint32_t g_kraw[S_LEN * DIM / 2];   // k pre-norm, fp16 pairs

__device__ uint4 g_x16[S_LEN * DIM / 8];    // x single fp16
__device__ uint4 g_w16[3 * DIM * DIM / 8];  // wq|wk|wv single fp16
__device__ uint4 g_wo16[DIM * DIM / 8];     // wo single fp16
__device__ uint4 g_q16[S_LEN * DIM / 8];    // Q single fp16 (post norm/rope)
__device__ uint4 g_k16[S_LEN * DIM / 8];    // K single fp16
__device__ uint4 g_v16[S_LEN * DIM / 8];    // V single fp16
__device__ uint4 g_ao16[S_LEN * DIM / 8];   // attn out single fp16
__device__ float g_opart[NSPLIT * S_LEN * DIM];  // split-KV O partials (fp32)
__device__ float g_lpart[NSPLIT * S_LEN * NH];   // split-KV l partials

// ---------------- PTX helpers ------------------------------------------------
__device__ __forceinline__ uint32_t smem_u32(const void* p) {
    uint32_t a;
    asm("{ .reg .u64 t; cvta.to.shared.u64 t, %1; cvt.u32.u64 %0, t; }" : "=r"(a) : "l"(p));
    return a;
}
__device__ __forceinline__ void ldsm_x4(uint32_t* r, uint32_t addr) {
    asm volatile("ldmatrix.sync.aligned.m8n8.x4.shared.b16 {%0,%1,%2,%3}, [%4];"
        : "=r"(r[0]), "=r"(r[1]), "=r"(r[2]), "=r"(r[3]) : "r"(addr));
}
__device__ __forceinline__ void ldsm_x4_t(uint32_t* r, uint32_t addr) {
    asm volatile("ldmatrix.sync.aligned.m8n8.x4.trans.shared.b16 {%0,%1,%2,%3}, [%4];"
        : "=r"(r[0]), "=r"(r[1]), "=r"(r[2]), "=r"(r[3]) : "r"(addr));
}
__device__ __forceinline__ void mma_f16(float* c, const uint32_t* a, const uint32_t* b) {
    asm volatile(
        "mma.sync.aligned.m16n8k16.row.col.f32.f16.f16.f32 "
        "{%0,%1,%2,%3}, {%4,%5,%6,%7}, {%8,%9}, {%0,%1,%2,%3};"
        : "+f"(c[0]), "+f"(c[1]), "+f"(c[2]), "+f"(c[3])
        : "r"(a[0]), "r"(a[1]), "r"(a[2]), "r"(a[3]), "r"(b[0]), "r"(b[1]));
}
__device__ __forceinline__ void cp16(uint32_t dst, const void* src) {
    asm volatile("cp.async.cg.shared.global [%0], [%1], 16;" :: "r"(dst), "l"(src));
}
#define CP_COMMIT()  asm volatile("cp.async.commit_group;" ::: "memory")
#define CP_WAIT(n)   asm volatile("cp.async.wait_group %0;" :: "n"(n) : "memory")

__device__ __forceinline__ uint32_t pack2h(float v0, float v1) {
    __half h0 = __float2half_rn(v0);
    __half h1 = __float2half_rn(v1);
    return (uint32_t)__half_as_ushort(h0) | ((uint32_t)__half_as_ushort(h1) << 16);
}
// p = 2^t for a pair: cvt fp32x2 -> f16x2, then paired MUFU exp
__device__ __forceinline__ uint32_t exp2_pair(float t_lo, float t_hi) {
    uint32_t d;
    asm("cvt.rn.f16x2.f32 %0, %1, %2;" : "=r"(d) : "f"(t_hi), "f"(t_lo));
    asm("ex2.approx.f16x2 %0, %0;" : "+r"(d));
    return d;
}

// ---------------- conversions --------------------------------------------------
__global__ __launch_bounds__(256)
void conv_h1(const float4* __restrict__ src, uint4* __restrict__ dst, int n8)
{
    int idx = blockIdx.x * blockDim.x + threadIdx.x;
    if (idx >= n8) return;
    float4 a = src[2 * idx], b = src[2 * idx + 1];
    dst[idx] = make_uint4(pack2h(a.x, a.y), pack2h(a.z, a.w),
                          pack2h(b.x, b.y), pack2h(b.z, b.w));
}

__global__ __launch_bounds__(256)
void conv_h1_w4(const float4* __restrict__ w0, const float4* __restrict__ w1,
                const float4* __restrict__ w2, const float4* __restrict__ w3,
                uint4* __restrict__ dst012, uint4* __restrict__ dst3, int n8)
{
    int idx = blockIdx.x * blockDim.x + threadIdx.x;
    if (idx >= n8) return;
    int y = blockIdx.y;
    const float4* src = (y == 0) ? w0 : (y == 1) ? w1 : (y == 2) ? w2 : w3;
    uint4* dst = (y < 3) ? (dst012 + (size_t)y * n8) : dst3;
    float4 a = src[2 * idx], b = src[2 * idx + 1];
    dst[idx] = make_uint4(pack2h(a.x, a.y), pack2h(a.z, a.w),
                          pack2h(b.x, b.y), pack2h(b.z, b.w));
}

// ---------------- fp16 1-term GEMM, BK=64, 3-stage single-barrier ring --------
// (R15 ordering: prefetch issued at stage top, before ldsm/MMA)
#define PITCH  144
#define TILEB  (128 * PITCH)
#define STAGEB (2 * TILEB)
#define GEMM_SMEM (3 * STAGEB)
#define NSTAGE 24

__global__ __launch_bounds__(256, 2)
void gemm_mma(const uint4* __restrict__ A16, const uint4* __restrict__ W16,
              const float* __restrict__ b0, const float* __restrict__ b1,
              const float* __restrict__ b2,
              void* __restrict__ C0v, void* __restrict__ C1v,
              uint32_t* __restrict__ V16,
              int ntw, int c_half)
{
    extern __shared__ char smc[];
    const uint32_t sb = smem_u32(smc);
    const int tid  = threadIdx.x;
    const int wid  = tid >> 5;
    const int lane = tid & 31;
    const int warp_m = wid & 3;
    const int warp_n = wid >> 2;

    const int m0     = blockIdx.x * 128;
    const int ntile  = blockIdx.y;
    const int w      = ntile / ntw;
    const int ncol0  = (ntile % ntw) * 128;
    const size_t wrow0 = (size_t)ntile * 128;

    const int lr = tid >> 3;
    const int lj = tid & 7;

    float acc[2][8][4];
#pragma unroll
    for (int i = 0; i < 2; i++)
#pragma unroll
        for (int j = 0; j < 8; j++)
#pragma unroll
            for (int k = 0; k < 4; k++) acc[i][j][k] = 0.f;

    auto prefetch = [&](int c, int buf) {
        const uint32_t st = sb + buf * STAGEB;
        const int kc8 = c * 8;
#pragma unroll
        for (int i = 0; i < 4; i++) {
            int r = lr + i * 32;
            uint32_t so = (uint32_t)(r * PITCH + lj * 16);
            size_t ga = (size_t)(m0 + r) * (DIM / 8) + kc8 + lj;
            cp16(st + 0 * TILEB + so, A16 + ga);
            size_t gb = (wrow0 + r) * (DIM / 8) + kc8 + lj;
            cp16(st + 1 * TILEB + so, W16 + gb);
        }
        CP_COMMIT();
    };

    prefetch(0, 0);
    prefetch(1, 1);

    const uint32_t a_lo = (uint32_t)((warp_m * 32 + (lane & 15)) * PITCH + (lane >> 4) * 16);
    const uint32_t b_lo = (uint32_t)((warp_n * 64 + (lane & 7) + ((lane >> 4) << 3)) * PITCH
                                     + ((lane >> 3) & 1) * 16);

    for (int c = 0; c < NSTAGE; c++) {
        if (c < NSTAGE - 1) { CP_WAIT(1); } else { CP_WAIT(0); }
        __syncthreads();
        if (c + 2 < NSTAGE) prefetch(c + 2, (c + 2) % 3);

        const uint32_t st = sb + (c % 3) * STAGEB;
#pragma unroll
        for (int ks = 0; ks < 4; ks++) {
            uint32_t ah[2][4], bh[4][4];
#pragma unroll
            for (int mt = 0; mt < 2; mt++) {
                ldsm_x4(ah[mt], st + mt * (16 * PITCH) + ks * 32 + a_lo);
            }
#pragma unroll
            for (int np = 0; np < 4; np++) {
                ldsm_x4(bh[np], st + 1 * TILEB + np * (16 * PITCH) + ks * 32 + b_lo);
            }
#pragma unroll
            for (int mt = 0; mt < 2; mt++) {
#pragma unroll
                for (int nt = 0; nt < 8; nt++) {
                    const uint32_t* bhp = &bh[nt >> 1][(nt & 1) * 2];
                    mma_f16(acc[mt][nt], ah[mt], bhp);
                }
            }
        }
    }

    const float* bias = (w == 0) ? b0 : (w == 1) ? b1 : b2;
    const int g = lane >> 2, t4 = lane & 3;

    if (w < 2) {
        if (c_half) {
            uint32_t* C = (uint32_t*)((w == 0) ? C0v : C1v);
#pragma unroll
            for (int mt = 0; mt < 2; mt++) {
                int row = m0 + warp_m * 32 + mt * 16 + g;
#pragma unroll
                for (int nt = 0; nt < 8; nt++) {
                    int col = ncol0 + warp_n * 64 + nt * 8 + t4 * 2;
                    float2 bv = *(const float2*)(bias + col);
                    size_t i0 = ((size_t)row * DIM + col) >> 1;
                    size_t i1 = ((size_t)(row + 8) * DIM + col) >> 1;
                    C[i0] = pack2h(acc[mt][nt][0] + bv.x, acc[mt][nt][1] + bv.y);
                    C[i1] = pack2h(acc[mt][nt][2] + bv.x, acc[mt][nt][3] + bv.y);
                }
            }
        } else {
            float* C = (float*)((w == 0) ? C0v : C1v);
#pragma unroll
            for (int mt = 0; mt < 2; mt++) {
                int row = m0 + warp_m * 32 + mt * 16 + g;
#pragma unroll
                for (int nt = 0; nt < 8; nt++) {
                    int col = ncol0 + warp_n * 64 + nt * 8 + t4 * 2;
                    float2 bv = *(const float2*)(bias + col);
                    float2 o0, o1;
                    o0.x = acc[mt][nt][0] + bv.x;  o0.y = acc[mt][nt][1] + bv.y;
                    o1.x = acc[mt][nt][2] + bv.x;  o1.y = acc[mt][nt][3] + bv.y;
                    *(float2*)(C + (size_t)row * DIM + col)       = o0;
                    *(float2*)(C + (size_t)(row + 8) * DIM + col) = o1;
                }
            }
        }
    } else {
#pragma unroll
        for (int mt = 0; mt < 2; mt++) {
            int row = m0 + warp_m * 32 + mt * 16 + g;
#pragma unroll
            for (int nt = 0; nt < 8; nt++) {
                int col = ncol0 + warp_n * 64 + nt * 8 + t4 * 2;
                float2 bv = *(const float2*)(bias + col);
                size_t i0 = ((size_t)row * DIM + col) >> 1;
                size_t i1 = ((size_t)(row + 8) * DIM + col) >> 1;
                V16[i0] = pack2h(acc[mt][nt][0] + bv.x, acc[mt][nt][1] + bv.y);
                V16[i1] = pack2h(acc[mt][nt][2] + bv.x, acc[mt][nt][3] + bv.y);
            }
        }
    }
}

// ---------------- fused RMSNorm + RoPE (fp16 in) -> single fp16 Q/K -----------
__global__ __launch_bounds__(256)
void norm_rope_split(const uint32_t* __restrict__ Qp, const uint32_t* __restrict__ Kp,
                     const float* __restrict__ gq, const float* __restrict__ gk,
                     const float* __restrict__ freqs, const int* __restrict__ grid_sizes,
                     uint32_t* __restrict__ Q16, uint32_t* __restrict__ K16)
{
    const int s   = blockIdx.x;
    const int tid = threadIdx.x;
    const int lane = tid & 31;
    const int wrp  = tid >> 5;
    __shared__ float redq[8], redk[8];
    __shared__ float s_rq, s_rk;

    const uint32_t* qrow = Qp + (size_t)s * (DIM / 2);
    const uint32_t* krow = Kp + (size_t)s * (DIM / 2);

    float sq = 0.f, sk = 0.f;
    for (int i = tid; i < DIM / 2; i += 256) {
        float2 a = __half22float2(*(const __half2*)(qrow + i));
        float2 b = __half22float2(*(const __half2*)(krow + i));
        sq += a.x * a.x + a.y * a.y;
        sk += b.x * b.x + b.y * b.y;
    }
#pragma unroll
    for (int off = 16; off > 0; off >>= 1) {
        sq += __shfl_xor_sync(0xffffffffu, sq, off);
        sk += __shfl_xor_sync(0xffffffffu, sk, off);
    }
    if (lane == 0) { redq[wrp] = sq; redk[wrp] = sk; }
    __syncthreads();
    if (wrp == 0) {
        float a = (lane < 8) ? redq[lane] : 0.f;
        float b = (lane < 8) ? redk[lane] : 0.f;
#pragma unroll
        for (int off = 4; off > 0; off >>= 1) {
            a += __shfl_xor_sync(0xffffffffu, a, off);
            b += __shfl_xor_sync(0xffffffffu, b, off);
        }
        if (lane == 0) {
            s_rq = rsqrtf(a * (1.f / DIM) + 1e-6f);
            s_rk = rsqrtf(b * (1.f / DIM) + 1e-6f);
        }
    }
    __syncthreads();

    const float rq = s_rq, rk = s_rk;

    const int hdim = grid_sizes[1];
    const int wdim = grid_sizes[2];
    const int wi = s % wdim;
    const int hi = (s / wdim) % hdim;
    const int fi = s / (wdim * hdim);

    for (int p = tid; p < NH * CHALF; p += 256) {
        const int head = p >> 6;
        const int c    = p & 63;
        int pos = (c < SEG0) ? fi : ((c < SEG0 + SEG1) ? hi : wi);
        float ang = freqs[(size_t)pos * CHALF + c];
        float sn, cs;
        __sincosf(ang, &sn, &cs);

        const int i32 = head * CHALF + c;
        const int d0  = 2 * i32;
        float2 qp = __half22float2(*(const __half2*)(qrow + i32));
        float2 kp = __half22float2(*(const __half2*)(krow + i32));

        float q0 = qp.x * rq * gq[d0];
        float q1 = qp.y * rq * gq[d0 + 1];
        float qv0 = q0 * cs - q1 * sn;
        float qv1 = q0 * sn + q1 * cs;

        float k0 = kp.x * rk * gk[d0];
        float k1 = kp.y * rk * gk[d0 + 1];
        float kv0 = k0 * cs - k1 * sn;
        float kv1 = k0 * sn + k1 * cs;

        size_t gi = (size_t)s * (DIM / 2) + i32;
        Q16[gi] = pack2h(qv0, qv1);
        K16[gi] = pack2h(kv0, kv1);
    }
}

// ---------------- flash attention: split-KV x3, f16x2 exp (R15 ordering) ------
#define FQT    128
#define FKT    64
#define FPITCH 272
#define K_O    0
#define V_O    (64 * FPITCH)
#define SLOT_SZ (2 * 64 * FPITCH)
#define FL_SMEM (3 * SLOT_SZ)           // Q staged in slot 2
#define SM_SHIFT 4.0f
#define LOG2E    1.44269504f
#define NT_TOT (S_LEN / FKT)            // 32 tiles total
#define NT_BASE 11                      // z=0:11, z=1:11, z=2:10

__global__ __launch_bounds__(256, 2)
void flash_mma(const uint4* __restrict__ Q16, const uint4* __restrict__ K16,
               const uint4* __restrict__ V16,
               float* __restrict__ Opart, float* __restrict__ Lpart,
               const int* __restrict__ seq_lens, float qscale)
{
    extern __shared__ char smc[];
    const uint32_t sb = smem_u32(smc);
    const int tid  = threadIdx.x;
    const int wid  = tid >> 5;
    const int lane = tid & 31;
    const int g    = lane >> 2;
    const int t4   = lane & 3;
    const int head = blockIdx.y;
    const int q0   = blockIdx.x * FQT;
    const int z    = blockIdx.z;
    const int t0   = z * NT_BASE;
    const int ntl  = (t0 + NT_BASE <= NT_TOT) ? NT_BASE : (NT_TOT - t0);
    const int seqlen = seq_lens[0];

    const int DIM8 = DIM / 8;
    const int h8   = head * (HD / 8);
    const float c2 = qscale * LOG2E;
    const float sh2 = SM_SHIFT * LOG2E;

    // stage Q into slot 2
    const uint32_t qst = sb + 2 * SLOT_SZ;
#pragma unroll
    for (int i = 0; i < 8; i++) {
        int t = tid + 256 * i;
        int r = t >> 4, j = t & 15;
        uint32_t so = (uint32_t)(r * FPITCH + j * 16);
        size_t gi = (size_t)(q0 + r) * DIM8 + h8 + j;
        cp16(qst + so, Q16 + gi);
    }
    CP_COMMIT();

    auto load_kv = [&](int kt, int slot) {
        uint32_t st = sb + slot * SLOT_SZ;
        int kr0 = kt * FKT;
#pragma unroll
        for (int i = 0; i < 4; i++) {
            int t = tid + 256 * i;
            int r = t >> 4, j = t & 15;
            uint32_t so = (uint32_t)(r * FPITCH + j * 16);
            size_t gi = (size_t)(kr0 + r) * DIM8 + h8 + j;
            cp16(st + K_O + so, K16 + gi);
            cp16(st + V_O + so, V16 + gi);
        }
        CP_COMMIT();
    };

    const uint32_t a_off  = (uint32_t)((wid * 16 + (lane & 15)) * FPITCH + (lane >> 4) * 16);
    const uint32_t bk_off = (uint32_t)(((lane & 7) + ((lane >> 4) << 3)) * FPITCH
                                       + ((lane >> 3) & 1) * 16);
    const uint32_t bv_row = (uint32_t)((lane & 7) + (((lane >> 3) & 1) << 3));
    const uint32_t bv_col = (uint32_t)((lane >> 4) * 16);

    CP_WAIT(0);
    __syncthreads();
    uint32_t qf[8][4];
#pragma unroll
    for (int kk = 0; kk < 8; kk++) {
        ldsm_x4(qf[kk], qst + a_off + kk * 32);
    }

    load_kv(t0 + 0, 0);
    load_kv(t0 + 1, 1);

    float o[16][4];
#pragma unroll
    for (int i = 0; i < 16; i++)
#pragma unroll
        for (int j = 0; j < 4; j++) o[i][j] = 0.f;
    float lacc[4] = {0.f, 0.f, 0.f, 0.f};
    const uint32_t ones2[2] = {0x3C003C00u, 0x3C003C00u};

    for (int kt = 0; kt < ntl; kt++) {
        if (kt < ntl - 1) { CP_WAIT(1); } else { CP_WAIT(0); }
        __syncthreads();
        if (kt + 2 < ntl) load_kv(t0 + kt + 2, (kt + 2) % 3);

        const uint32_t st = sb + (kt % 3) * SLOT_SZ;

        // ---- scores ----
        float acc[8][4];
#pragma unroll
        for (int i = 0; i < 8; i++)
#pragma unroll
            for (int j = 0; j < 4; j++) acc[i][j] = 0.f;

#pragma unroll
        for (int kk = 0; kk < 8; kk++) {
#pragma unroll
            for (int np = 0; np < 4; np++) {
                uint32_t bh[4];
                ldsm_x4(bh, st + K_O + np * (16 * FPITCH) + bk_off + kk * 32);
                mma_f16(acc[2*np],   qf[kk], &bh[0]);
                mma_f16(acc[2*np+1], qf[kk], &bh[2]);
            }
        }

        // ---- fixed-shift softmax via paired f16 exp ----
        const int kr0 = (t0 + kt) * FKT;
        uint32_t ph0[8], ph1[8];
#pragma unroll
        for (int j = 0; j < 8; j++) {
            float t00 = fmaf(acc[j][0], c2, -sh2);
            float t01 = fmaf(acc[j][1], c2, -sh2);
            float t10 = fmaf(acc[j][2], c2, -sh2);
            float t11 = fmaf(acc[j][3], c2, -sh2);
            int c0 = kr0 + 8 * j + 2 * t4;
            if (c0 >= seqlen)     { t00 = -1e30f; t10 = -1e30f; }
            if (c0 + 1 >= seqlen) { t01 = -1e30f; t11 = -1e30f; }
            ph0[j] = exp2_pair(t00, t01);
            ph1[j] = exp2_pair(t10, t11);
        }

        // ---- PV + l (ones-column MMA) ----
#pragma unroll
        for (int k2 = 0; k2 < 4; k2++) {
            uint32_t aph[4] = { ph0[2*k2], ph1[2*k2], ph0[2*k2+1], ph1[2*k2+1] };
            mma_f16(lacc, aph, ones2);
            uint32_t vrow = st + V_O + (uint32_t)((k2 * 16 + bv_row) * FPITCH) + bv_col;
#pragma unroll
            for (int d = 0; d < 8; d++) {
                uint32_t bv[4];
                ldsm_x4_t(bv, vrow + d * 32);
                mma_f16(o[2*d],   aph, &bv[0]);
                mma_f16(o[2*d+1], aph, &bv[2]);
            }
        }
    }

    // ---- fp32 partial epilogue ----
    const int row0 = q0 + wid * 16 + g;
    float* Op = Opart + (size_t)z * S_LEN * DIM;
    if (t4 == 0) {
        Lpart[(size_t)z * S_LEN * NH + (size_t)row0 * NH + head]       = lacc[0];
        Lpart[(size_t)z * S_LEN * NH + (size_t)(row0 + 8) * NH + head] = lacc[2];
    }
#pragma unroll
    for (int nt = 0; nt < 16; nt++) {
        int col = head * HD + nt * 8 + 2 * t4;
        *(float2*)(Op + (size_t)row0 * DIM + col)       = make_float2(o[nt][0], o[nt][1]);
        *(float2*)(Op + (size_t)(row0 + 8) * DIM + col) = make_float2(o[nt][2], o[nt][3]);
    }
}

// ---------------- split-KV combine: sum(Oz)/sum(lz) -> fp16 -------------------
__global__ __launch_bounds__(256)
void combine_kv(const float* __restrict__ Opart, const float* __restrict__ Lpart,
                uint32_t* __restrict__ AO16)
{
    int e4 = blockIdx.x * 256 + threadIdx.x;
    if (e4 >= S_LEN * DIM / 4) return;
    size_t base = (size_t)e4 * 4;
    int row = (int)(base / DIM);
    int col = (int)(base % DIM);
    int h = col >> 7;
    float l = 0.f;
    float4 s = make_float4(0.f, 0.f, 0.f, 0.f);
#pragma unroll
    for (int z = 0; z < NSPLIT; z++) {
        l += Lpart[(size_t)z * S_LEN * NH + (size_t)row * NH + h];
        float4 a = *(const float4*)(Opart + (size_t)z * S_LEN * DIM + base);
        s.x += a.x; s.y += a.y; s.z += a.z; s.w += a.w;
    }
    float inv = 1.f / l;
    AO16[e4 * 2 + 0] = pack2h(s.x * inv, s.y * inv);
    AO16[e4 * 2 + 1] = pack2h(s.z * inv, s.w * inv);
}

// ---------------- launcher ---------------------------------------------------
extern "C" void kernel_launch(void* const* d_in, const int* in_sizes, int n_in,
                              void* d_out, int out_size)
{
    const float* x     = (const float*)d_in[0];
    const float* freqs = (const float*)d_in[1];
    const float* wq    = (const float*)d_in[2];
    const float* bq    = (const float*)d_in[3];
    const float* wk    = (const float*)d_in[4];
    const float* bk    = (const float*)d_in[5];
    const float* wv    = (const float*)d_in[6];
    const float* bv    = (const float*)d_in[7];
    const float* wo    = (const float*)d_in[8];
    const float* bo    = (const float*)d_in[9];
    const float* gq    = (const float*)d_in[10];
    const float* gk    = (const float*)d_in[11];
    const int*   seq_lens   = (const int*)d_in[12];
    const int*   grid_sizes = (const int*)d_in[13];
    float* out = (float*)d_out;

    uint32_t *qraw, *kraw;
    float *opart, *lpart;
    uint4 *x16, *w16, *wo16, *q16, *k16, *v16, *ao16;
    cudaGetSymbolAddress((void**)&qraw,  g_qraw);
    cudaGetSymbolAddress((void**)&kraw,  g_kraw);
    cudaGetSymbolAddress((void**)&x16,   g_x16);
    cudaGetSymbolAddress((void**)&w16,   g_w16);
    cudaGetSymbolAddress((void**)&wo16,  g_wo16);
    cudaGetSymbolAddress((void**)&q16,   g_q16);
    cudaGetSymbolAddress((void**)&k16,   g_k16);
    cudaGetSymbolAddress((void**)&v16,   g_v16);
    cudaGetSymbolAddress((void**)&ao16,  g_ao16);
    cudaGetSymbolAddress((void**)&opart, g_opart);
    cudaGetSymbolAddress((void**)&lpart, g_lpart);

    const int n8x = S_LEN * DIM / 8;
    const int n8w = DIM * DIM / 8;
    const float qscale = 1.0f / sqrtf((float)HD);

    conv_h1<<<(n8x + 255) / 256, 256>>>((const float4*)x, x16, n8x);
    conv_h1_w4<<<dim3((n8w + 255) / 256, 4), 256>>>(
        (const float4*)wq, (const float4*)wk, (const float4*)wv, (const float4*)wo,
        w16, wo16, n8w);

    cudaFuncSetAttribute(gemm_mma, cudaFuncAttributeMaxDynamicSharedMemorySize, GEMM_SMEM);

    // fused QKV: q,k written as fp16; V fp16
    gemm_mma<<<dim3(S_LEN / 128, 36), 256, GEMM_SMEM>>>(
        x16, w16, bq, bk, bv, qraw, kraw, (uint32_t*)v16, DIM / 128, 1);

    norm_rope_split<<<S_LEN, 256>>>(qraw, kraw, gq, gk, freqs, grid_sizes,
                                    (uint32_t*)q16, (uint32_t*)k16);

    cudaFuncSetAttribute(flash_mma, cudaFuncAttributeMaxDynamicSharedMemorySize, FL_SMEM);
    flash_mma<<<dim3(S_LEN / FQT, NH, NSPLIT), 256, FL_SMEM>>>(
        q16, k16, v16, opart, lpart, seq_lens, qscale);

    combine_kv<<<(S_LEN * DIM / 4 + 255) / 256, 256>>>(opart, lpart, (uint32_t*)ao16);

    // output projection: fp32 C
    gemm_mma<<<dim3(S_LEN / 128, 12), 256, GEMM_SMEM>>>(
        ao16, wo16, bo, bo, bo, out, (void*)out, (uint32_t*)v16, DIM / 128, 0);
}